// round 1
// baseline (speedup 1.0000x reference)
#include <cuda_runtime.h>
#include <math.h>

// Problem constants (from reference setup_inputs)
#define T_TOK 4096      // B*S = 2*2048 tokens
#define D_DIM 1024
#define F_DIM 2048
#define E_NUM 8
#define NGRP  9         // group 0 = shared expert, groups 1..8 = routed experts 0..7
#define MAXROWS (3*T_TOK)  // T shared rows + 2T routed rows = 12288

// ---------------- device scratch (static globals; no allocations) ----------------
__device__ int   g_cnt[E_NUM];
__device__ int   g_fill[E_NUM];
__device__ int   g_start[NGRP];
__device__ int   g_gcnt[NGRP];
__device__ int   g_topi[T_TOK * 2];
__device__ float g_topw[T_TOK * 2];
__device__ int   g_tok[MAXROWS];       // assignment row -> token index
__device__ float g_wt[MAXROWS];        // assignment row -> combine weight
__device__ int   g_rowof[T_TOK * 2];   // token,slot -> assignment row
__device__ float g_H[(size_t)MAXROWS * F_DIM];  // gelu(up) activations, ~100.7 MB
__device__ float g_Y[(size_t)MAXROWS * D_DIM];  // weighted down-proj rows, ~50.3 MB

// ---------------- init: zero the atomic counters each invocation ----------------
__global__ void init_kernel() {
    int i = threadIdx.x;
    if (i < E_NUM) { g_cnt[i] = 0; g_fill[i] = 0; }
}

// ---------------- router: logits -> top-2 -> renormalized weights ----------------
// One warp per token. Renormalized top-2 softmax == sigmoid of logit difference:
//   w0 = exp(l0)/(exp(l0)+exp(l1)) = 1/(1+exp(l1-l0))
__global__ void router_kernel(const float* __restrict__ x,
                              const float* __restrict__ Wg) {
    int warp = (blockIdx.x * blockDim.x + threadIdx.x) >> 5;
    int lane = threadIdx.x & 31;
    if (warp >= T_TOK) return;
    const float* xr = x + (size_t)warp * D_DIM;

    float acc[E_NUM];
#pragma unroll
    for (int e = 0; e < E_NUM; e++) acc[e] = 0.f;

    for (int i = 0; i < D_DIM / 32; i++) {
        int d = i * 32 + lane;
        float xv = xr[d];
        const float4* wr = (const float4*)(Wg + (size_t)d * E_NUM);
        float4 w0 = wr[0], w1 = wr[1];
        acc[0] += xv * w0.x; acc[1] += xv * w0.y;
        acc[2] += xv * w0.z; acc[3] += xv * w0.w;
        acc[4] += xv * w1.x; acc[5] += xv * w1.y;
        acc[6] += xv * w1.z; acc[7] += xv * w1.w;
    }
#pragma unroll
    for (int e = 0; e < E_NUM; e++)
#pragma unroll
        for (int o = 16; o > 0; o >>= 1)
            acc[e] += __shfl_down_sync(0xffffffffu, acc[e], o);

    if (lane == 0) {
        int b0 = -1, b1 = -1;
        float v0 = -1e30f, v1 = -1e30f;
#pragma unroll
        for (int e = 0; e < E_NUM; e++) {
            float v = acc[e];
            if (v > v0) { v1 = v0; b1 = b0; v0 = v; b0 = e; }
            else if (v > v1) { v1 = v; b1 = e; }
        }
        float w0 = 1.f / (1.f + expf(v1 - v0));
        g_topi[warp * 2 + 0] = b0; g_topw[warp * 2 + 0] = w0;
        g_topi[warp * 2 + 1] = b1; g_topw[warp * 2 + 1] = 1.f - w0;
        atomicAdd(&g_cnt[b0], 1);
        atomicAdd(&g_cnt[b1], 1);
    }
}

// ---------------- tiny exclusive scan over 8 expert counts ----------------
__global__ void scan_kernel() {
    g_start[0] = 0; g_gcnt[0] = T_TOK;   // shared-expert group: rows [0, T)
    int off = T_TOK;
    for (int e = 0; e < E_NUM; e++) {
        g_start[e + 1] = off;
        g_gcnt[e + 1]  = g_cnt[e];
        off += g_cnt[e];
    }
}

// ---------------- bucket fill: token -> assignment rows ----------------
__global__ void fill_kernel() {
    int t = blockIdx.x * blockDim.x + threadIdx.x;
    if (t >= T_TOK) return;
    g_tok[t] = t; g_wt[t] = 1.f;         // shared row = token id
#pragma unroll
    for (int j = 0; j < 2; j++) {
        int e = g_topi[t * 2 + j];
        int r = g_start[e + 1] + atomicAdd(&g_fill[e], 1);
        g_tok[r] = t;
        g_wt[r]  = g_topw[t * 2 + j];
        g_rowof[t * 2 + j] = r;
    }
}

__device__ __forceinline__ float gelu_erf(float v) {
    return 0.5f * v * (1.f + erff(v * 0.70710678118654752440f));
}

// ---------------- grouped 128x128x8 fp32 SGEMM ----------------
// UP  : C = gelu(gather(X) @ B),  X rows gathered via g_tok, B in {Wu[e], W1}, C = g_H
// !UP : C = wt * (g_H @ B),       contiguous rows,          B in {Wd[e], W2}, C = g_Y
template<int KDIM, int NDIM, bool UP>
__global__ __launch_bounds__(256)
void grouped_gemm_kernel(const float* __restrict__ X,
                         const float* __restrict__ Bexp,
                         const float* __restrict__ Bsh) {
    __shared__ float As[8][132];   // padded: transposed A tile
    __shared__ float Bs[8][128];

    const int g   = blockIdx.z;
    const int cnt = g_gcnt[g];
    const int m0  = blockIdx.x * 128;
    if (m0 >= cnt) return;
    const int start = g_start[g];
    const int n0    = blockIdx.y * 128;

    const float* __restrict__ B =
        (g == 0) ? Bsh : (Bexp + (size_t)(g - 1) * KDIM * NDIM);
    const float* __restrict__ Asrc = UP ? X : g_H;
    float* __restrict__ Cdst = UP ? g_H : g_Y;

    const int tid  = threadIdx.x;
    const int arow = tid >> 1;          // 0..127
    const int ak   = (tid & 1) << 2;    // 0 or 4
    const int brow = tid >> 5;          // 0..7
    const int bcol = (tid & 31) << 2;   // 0..124
    const int ty   = tid >> 4;          // 0..15
    const int tx   = tid & 15;          // 0..15

    // Row pointer for this thread's A-tile load (clamped for the ragged tail)
    int grow = m0 + arow;
    int srcrow;
    if (UP) srcrow = (grow < cnt) ? g_tok[start + grow] : 0;
    else    srcrow = (grow < cnt) ? (start + grow) : start;
    const float* __restrict__ arp = Asrc + (size_t)srcrow * KDIM;

    float c[8][8];
#pragma unroll
    for (int i = 0; i < 8; i++)
#pragma unroll
        for (int j = 0; j < 8; j++) c[i][j] = 0.f;

    for (int kt = 0; kt < KDIM / 8; kt++) {
        float4 av = *(const float4*)(arp + kt * 8 + ak);
        float4 bv = *(const float4*)(B + (size_t)(kt * 8 + brow) * NDIM + n0 + bcol);
        __syncthreads();   // previous tile's compute done
        As[ak + 0][arow] = av.x;
        As[ak + 1][arow] = av.y;
        As[ak + 2][arow] = av.z;
        As[ak + 3][arow] = av.w;
        *(float4*)&Bs[brow][bcol] = bv;
        __syncthreads();
#pragma unroll
        for (int k = 0; k < 8; k++) {
            float a[8], b[8];
            *(float4*)(a)     = *(const float4*)&As[k][ty * 8];
            *(float4*)(a + 4) = *(const float4*)&As[k][ty * 8 + 4];
            *(float4*)(b)     = *(const float4*)&Bs[k][tx * 8];
            *(float4*)(b + 4) = *(const float4*)&Bs[k][tx * 8 + 4];
#pragma unroll
            for (int i = 0; i < 8; i++)
#pragma unroll
                for (int j = 0; j < 8; j++)
                    c[i][j] = fmaf(a[i], b[j], c[i][j]);
        }
    }

    // Epilogue
#pragma unroll
    for (int i = 0; i < 8; i++) {
        int r = m0 + ty * 8 + i;
        if (r >= cnt) continue;
        size_t obase = (size_t)(start + r) * NDIM + n0 + tx * 8;
        float wt = UP ? 1.f : g_wt[start + r];
        float v[8];
#pragma unroll
        for (int j = 0; j < 8; j++) {
            float t = c[i][j];
            v[j] = UP ? gelu_erf(t) : t * wt;
        }
        *(float4*)(Cdst + obase)     = make_float4(v[0], v[1], v[2], v[3]);
        *(float4*)(Cdst + obase + 4) = make_float4(v[4], v[5], v[6], v[7]);
    }
}

// ---------------- combine: out[t] = Y_shared[t] + Y[r0] + Y[r1] ----------------
// (weights already applied in down-proj epilogue; fixed add order => deterministic)
__global__ void combine_kernel(float* __restrict__ out) {
    int i = blockIdx.x * blockDim.x + threadIdx.x;   // over T*D/4
    if (i >= T_TOK * (D_DIM / 4)) return;
    int t  = i / (D_DIM / 4);
    int c4 = i - t * (D_DIM / 4);
    int r0 = g_rowof[t * 2 + 0];
    int r1 = g_rowof[t * 2 + 1];
    float4 s = ((const float4*)(g_Y + (size_t)t  * D_DIM))[c4];
    float4 a = ((const float4*)(g_Y + (size_t)r0 * D_DIM))[c4];
    float4 b = ((const float4*)(g_Y + (size_t)r1 * D_DIM))[c4];
    float4 o;
    o.x = s.x + a.x + b.x;
    o.y = s.y + a.y + b.y;
    o.z = s.z + a.z + b.z;
    o.w = s.w + a.w + b.w;
    ((float4*)out)[i] = o;
}

// ---------------- launcher ----------------
extern "C" void kernel_launch(void* const* d_in, const int* in_sizes, int n_in,
                              void* d_out, int out_size) {
    const float* x  = (const float*)d_in[0];  // [T, D]
    const float* Wg = (const float*)d_in[1];  // [D, E]
    const float* Wu = (const float*)d_in[2];  // [E, D, F]
    const float* Wd = (const float*)d_in[3];  // [E, F, D]
    const float* W1 = (const float*)d_in[4];  // [D, F]
    const float* W2 = (const float*)d_in[5];  // [F, D]
    float* out = (float*)d_out;               // [T, D]

    init_kernel<<<1, 32>>>();
    router_kernel<<<T_TOK / 8, 256>>>(x, Wg);      // 8 warps/block
    scan_kernel<<<1, 1>>>();
    fill_kernel<<<(T_TOK + 255) / 256, 256>>>();

    // up-proj + GELU: M up to 4096/group, N = F = 2048, K = D = 1024
    grouped_gemm_kernel<D_DIM, F_DIM, true>
        <<<dim3(T_TOK / 128, F_DIM / 128, NGRP), 256>>>(x, Wu, W1);

    // down-proj + weight: M same, N = D = 1024, K = F = 2048
    grouped_gemm_kernel<F_DIM, D_DIM, false>
        <<<dim3(T_TOK / 128, D_DIM / 128, NGRP), 256>>>(nullptr, Wd, W2);

    combine_kernel<<<(T_TOK * (D_DIM / 4) + 255) / 256, 256>>>(out);
}

// round 2
// speedup vs baseline: 3.3198x; 3.3198x over previous
#include <cuda_runtime.h>
#include <cstdint>
#include <math.h>

// Problem constants (from reference setup_inputs)
#define T_TOK 4096      // B*S = 2*2048 tokens
#define D_DIM 1024
#define F_DIM 2048
#define E_NUM 8
#define NGRP  9         // group 0 = shared expert, groups 1..8 = routed experts
#define MAXROWS (3*T_TOK)

// ---------------- device scratch ----------------
__device__ int   g_cnt[E_NUM];
__device__ int   g_fill[E_NUM];
__device__ int   g_start[NGRP];
__device__ int   g_gcnt[NGRP];
__device__ int   g_topi[T_TOK * 2];
__device__ float g_topw[T_TOK * 2];
__device__ int   g_tok[MAXROWS];
__device__ float g_wt[MAXROWS];
__device__ int   g_rowof[T_TOK * 2];
__device__ float g_H[(size_t)MAXROWS * F_DIM];
__device__ float g_Y[(size_t)MAXROWS * D_DIM];

// ---------------- init ----------------
__global__ void init_kernel() {
    int i = threadIdx.x;
    if (i < E_NUM) { g_cnt[i] = 0; g_fill[i] = 0; }
}

// ---------------- router ----------------
__global__ void router_kernel(const float* __restrict__ x,
                              const float* __restrict__ Wg) {
    int warp = (blockIdx.x * blockDim.x + threadIdx.x) >> 5;
    int lane = threadIdx.x & 31;
    if (warp >= T_TOK) return;
    const float* xr = x + (size_t)warp * D_DIM;

    float acc[E_NUM];
#pragma unroll
    for (int e = 0; e < E_NUM; e++) acc[e] = 0.f;

    for (int i = 0; i < D_DIM / 32; i++) {
        int d = i * 32 + lane;
        float xv = xr[d];
        const float4* wr = (const float4*)(Wg + (size_t)d * E_NUM);
        float4 w0 = wr[0], w1 = wr[1];
        acc[0] += xv * w0.x; acc[1] += xv * w0.y;
        acc[2] += xv * w0.z; acc[3] += xv * w0.w;
        acc[4] += xv * w1.x; acc[5] += xv * w1.y;
        acc[6] += xv * w1.z; acc[7] += xv * w1.w;
    }
#pragma unroll
    for (int e = 0; e < E_NUM; e++)
#pragma unroll
        for (int o = 16; o > 0; o >>= 1)
            acc[e] += __shfl_down_sync(0xffffffffu, acc[e], o);

    if (lane == 0) {
        int b0 = -1, b1 = -1;
        float v0 = -1e30f, v1 = -1e30f;
#pragma unroll
        for (int e = 0; e < E_NUM; e++) {
            float v = acc[e];
            if (v > v0) { v1 = v0; b1 = b0; v0 = v; b0 = e; }
            else if (v > v1) { v1 = v; b1 = e; }
        }
        float w0 = 1.f / (1.f + expf(v1 - v0));
        g_topi[warp * 2 + 0] = b0; g_topw[warp * 2 + 0] = w0;
        g_topi[warp * 2 + 1] = b1; g_topw[warp * 2 + 1] = 1.f - w0;
        atomicAdd(&g_cnt[b0], 1);
        atomicAdd(&g_cnt[b1], 1);
    }
}

__global__ void scan_kernel() {
    g_start[0] = 0; g_gcnt[0] = T_TOK;
    int off = T_TOK;
    for (int e = 0; e < E_NUM; e++) {
        g_start[e + 1] = off;
        g_gcnt[e + 1]  = g_cnt[e];
        off += g_cnt[e];
    }
}

__global__ void fill_kernel() {
    int t = blockIdx.x * blockDim.x + threadIdx.x;
    if (t >= T_TOK) return;
    g_tok[t] = t; g_wt[t] = 1.f;
#pragma unroll
    for (int j = 0; j < 2; j++) {
        int e = g_topi[t * 2 + j];
        int r = g_start[e + 1] + atomicAdd(&g_fill[e], 1);
        g_tok[r] = t;
        g_wt[r]  = g_topw[t * 2 + j];
        g_rowof[t * 2 + j] = r;
    }
}

__device__ __forceinline__ float gelu_erf(float v) {
    return 0.5f * v * (1.f + erff(v * 0.70710678118654752440f));
}

// ---------------- tf32 helpers ----------------
__device__ __forceinline__ uint32_t f2tf(float f) {
    uint32_t u;
    asm("cvt.rna.tf32.f32 %0, %1;" : "=r"(u) : "f"(f));
    return u;
}

__device__ __forceinline__ void mma_tf32(float c[4], const uint32_t a[4],
                                         const uint32_t b[2]) {
    asm("mma.sync.aligned.m16n8k8.row.col.f32.tf32.tf32.f32 "
        "{%0,%1,%2,%3},{%4,%5,%6,%7},{%8,%9},{%0,%1,%2,%3};"
        : "+f"(c[0]), "+f"(c[1]), "+f"(c[2]), "+f"(c[3])
        : "r"(a[0]), "r"(a[1]), "r"(a[2]), "r"(a[3]), "r"(b[0]), "r"(b[1]));
}

__device__ __forceinline__ void cp16(void* smem_dst, const void* gsrc) {
    uint32_t d = (uint32_t)__cvta_generic_to_shared(smem_dst);
    asm volatile("cp.async.ca.shared.global [%0], [%1], 16;\n" ::"r"(d), "l"(gsrc));
}

// ---------------- grouped TF32 tensor-core GEMM ----------------
// 128x128 block tile, BK=16, 8 warps as 2x4 (warp tile 64x32), mma m16n8k8,
// cp.async double buffering, cvt.rna on every fragment (unbiased tf32).
template<int KDIM, int NDIM, bool UP>
__global__ __launch_bounds__(256, 2)
void grouped_gemm_tf32(const float* __restrict__ X,
                       const float* __restrict__ Bexp,
                       const float* __restrict__ Bsh) {
    __shared__ float As[2][128][20];   // [buf][m][k], stride 20 -> conflict-free frags
    __shared__ float Bs[2][16][136];   // [buf][k][n], stride 136 -> conflict-free frags

    const int g   = blockIdx.z;
    const int cnt = g_gcnt[g];
    const int m0  = blockIdx.x * 128;
    if (m0 >= cnt) return;
    const int start = g_start[g];
    const int n0    = blockIdx.y * 128;

    const float* __restrict__ B =
        (g == 0) ? Bsh : (Bexp + (size_t)(g - 1) * KDIM * NDIM);
    const float* __restrict__ Asrc = UP ? X : g_H;
    float* __restrict__ Cdst = UP ? g_H : g_Y;

    const int tid  = threadIdx.x;
    const int warp = tid >> 5;
    const int lane = tid & 31;
    const int gid  = lane >> 2;   // 0..7
    const int tig  = lane & 3;    // 0..3
    const int wm   = (warp >> 2) * 64;   // warp row offset in tile
    const int wn   = (warp & 3) * 32;    // warp col offset in tile

    // --- cp.async source pointers (A rows gathered once) ---
    const int ra  = tid >> 2;           // A rows ra, ra+64
    const int c4a = (tid & 3) * 4;
    const int rb  = tid >> 5;           // B rows rb, rb+8
    const int c4b = (tid & 31) * 4;

    int gr0 = m0 + ra;       if (gr0 >= cnt) gr0 = cnt - 1;
    int gr1 = m0 + ra + 64;  if (gr1 >= cnt) gr1 = cnt - 1;
    int sr0, sr1;
    if (UP) { sr0 = g_tok[start + gr0]; sr1 = g_tok[start + gr1]; }
    else    { sr0 = start + gr0;        sr1 = start + gr1; }
    const float* pA0 = Asrc + (size_t)sr0 * KDIM + c4a;
    const float* pA1 = Asrc + (size_t)sr1 * KDIM + c4a;
    const float* pB  = B + n0 + c4b;

    float c[4][4][4];
#pragma unroll
    for (int i = 0; i < 4; i++)
#pragma unroll
        for (int j = 0; j < 4; j++)
#pragma unroll
            for (int k = 0; k < 4; k++) c[i][j][k] = 0.f;

    const int KT = KDIM / 16;

    // prologue: stage 0
    {
        cp16(&As[0][ra][c4a],      pA0);
        cp16(&As[0][ra + 64][c4a], pA1);
        cp16(&Bs[0][rb][c4b],      pB + (size_t)rb * NDIM);
        cp16(&Bs[0][rb + 8][c4b],  pB + (size_t)(rb + 8) * NDIM);
        asm volatile("cp.async.commit_group;");
    }

    for (int kt = 0; kt < KT; kt++) {
        const int cur = kt & 1;
        if (kt + 1 < KT) {
            const int nxt = cur ^ 1;
            const int kb = (kt + 1) * 16;
            cp16(&As[nxt][ra][c4a],      pA0 + kb);
            cp16(&As[nxt][ra + 64][c4a], pA1 + kb);
            cp16(&Bs[nxt][rb][c4b],      pB + (size_t)(kb + rb) * NDIM);
            cp16(&Bs[nxt][rb + 8][c4b],  pB + (size_t)(kb + rb + 8) * NDIM);
            asm volatile("cp.async.commit_group;");
            asm volatile("cp.async.wait_group 1;");
        } else {
            asm volatile("cp.async.wait_group 0;");
        }
        __syncthreads();

#pragma unroll
        for (int ks = 0; ks < 2; ks++) {
            uint32_t af[4][4], bf[4][2];
            const int kb = ks * 8;
#pragma unroll
            for (int mt = 0; mt < 4; mt++) {
                int row = wm + mt * 16 + gid;
                af[mt][0] = f2tf(As[cur][row][kb + tig]);
                af[mt][1] = f2tf(As[cur][row + 8][kb + tig]);
                af[mt][2] = f2tf(As[cur][row][kb + tig + 4]);
                af[mt][3] = f2tf(As[cur][row + 8][kb + tig + 4]);
            }
#pragma unroll
            for (int nt = 0; nt < 4; nt++) {
                int col = wn + nt * 8 + gid;
                bf[nt][0] = f2tf(Bs[cur][kb + tig][col]);
                bf[nt][1] = f2tf(Bs[cur][kb + tig + 4][col]);
            }
#pragma unroll
            for (int mt = 0; mt < 4; mt++)
#pragma unroll
                for (int nt = 0; nt < 4; nt++)
                    mma_tf32(c[mt][nt], af[mt], bf[nt]);
        }
        __syncthreads();
    }

    // ---------------- epilogue ----------------
#pragma unroll
    for (int mt = 0; mt < 4; mt++) {
        int r0 = m0 + wm + mt * 16 + gid;
        int r1 = r0 + 8;
        float w0 = 1.f, w1 = 1.f;
        if (!UP) {
            if (r0 < cnt) w0 = g_wt[start + r0];
            if (r1 < cnt) w1 = g_wt[start + r1];
        }
#pragma unroll
        for (int nt = 0; nt < 4; nt++) {
            int col = n0 + wn + nt * 8 + tig * 2;
            if (r0 < cnt) {
                float2 v;
                if (UP) { v.x = gelu_erf(c[mt][nt][0]); v.y = gelu_erf(c[mt][nt][1]); }
                else    { v.x = c[mt][nt][0] * w0;      v.y = c[mt][nt][1] * w0; }
                *(float2*)(Cdst + (size_t)(start + r0) * NDIM + col) = v;
            }
            if (r1 < cnt) {
                float2 v;
                if (UP) { v.x = gelu_erf(c[mt][nt][2]); v.y = gelu_erf(c[mt][nt][3]); }
                else    { v.x = c[mt][nt][2] * w1;      v.y = c[mt][nt][3] * w1; }
                *(float2*)(Cdst + (size_t)(start + r1) * NDIM + col) = v;
            }
        }
    }
}

// ---------------- combine ----------------
__global__ void combine_kernel(float* __restrict__ out) {
    int i = blockIdx.x * blockDim.x + threadIdx.x;
    if (i >= T_TOK * (D_DIM / 4)) return;
    int t  = i / (D_DIM / 4);
    int c4 = i - t * (D_DIM / 4);
    int r0 = g_rowof[t * 2 + 0];
    int r1 = g_rowof[t * 2 + 1];
    float4 s = ((const float4*)(g_Y + (size_t)t  * D_DIM))[c4];
    float4 a = ((const float4*)(g_Y + (size_t)r0 * D_DIM))[c4];
    float4 b = ((const float4*)(g_Y + (size_t)r1 * D_DIM))[c4];
    float4 o;
    o.x = s.x + a.x + b.x;
    o.y = s.y + a.y + b.y;
    o.z = s.z + a.z + b.z;
    o.w = s.w + a.w + b.w;
    ((float4*)out)[i] = o;
}

// ---------------- launcher ----------------
extern "C" void kernel_launch(void* const* d_in, const int* in_sizes, int n_in,
                              void* d_out, int out_size) {
    const float* x  = (const float*)d_in[0];
    const float* Wg = (const float*)d_in[1];
    const float* Wu = (const float*)d_in[2];
    const float* Wd = (const float*)d_in[3];
    const float* W1 = (const float*)d_in[4];
    const float* W2 = (const float*)d_in[5];
    float* out = (float*)d_out;

    init_kernel<<<1, 32>>>();
    router_kernel<<<T_TOK / 8, 256>>>(x, Wg);
    scan_kernel<<<1, 1>>>();
    fill_kernel<<<(T_TOK + 255) / 256, 256>>>();

    grouped_gemm_tf32<D_DIM, F_DIM, true>
        <<<dim3(T_TOK / 128, F_DIM / 128, NGRP), 256>>>(x, Wu, W1);

    grouped_gemm_tf32<F_DIM, D_DIM, false>
        <<<dim3(T_TOK / 128, D_DIM / 128, NGRP), 256>>>(nullptr, Wd, W2);

    combine_kernel<<<(T_TOK * (D_DIM / 4) + 255) / 256, 256>>>(out);
}